// round 3
// baseline (speedup 1.0000x reference)
#include <cuda_runtime.h>
#include <cuda_bf16.h>
#include <cuda_fp16.h>
#include <cstdint>

#define SEQ    256
#define BATCH  32
#define REC    16
#define EMB    32
#define VOCAB  32000
#define NROWS  (SEQ * BATCH)   // 8192
#define VS     4               // vocab splits
#define RPB    64              // rows per block (4 MMA fragments)
#define NF     4               // fragments per block

// ---- scratch ----
__device__ float          g_Apre[NROWS * REC];
__device__ __nv_bfloat16  g_hidden[NROWS * REC];    // hidden, bf16
__device__ __nv_bfloat16  g_hiddenL[NROWS * REC];   // hidden * log2(e), bf16
__device__ uint32_t       g_Vbp[VOCAB * 8];         // V bf16, MMA-permuted: [col][t] = {pair t, pair t+4}
__device__ float          g_part[VS][NROWS];

__device__ __forceinline__ float ex2f(float x) { float y; asm("ex2.approx.f32 %0, %1;" : "=f"(y) : "f"(x)); return y; }
__device__ __forceinline__ float lg2f(float x) { float y; asm("lg2.approx.f32 %0, %1;" : "=f"(y) : "f"(x)); return y; }
__device__ __forceinline__ float rcpf(float x) { float y; asm("rcp.approx.f32 %0, %1;" : "=f"(y) : "f"(x)); return y; }

#define L2E 1.4426950408889634f
#define LN2 0.6931471805599453f

__device__ __forceinline__ void mma16816(float d[4], const uint32_t a[4], uint32_t b0, uint32_t b1) {
    asm("mma.sync.aligned.m16n8k16.row.col.f32.bf16.bf16.f32 "
        "{%0,%1,%2,%3}, {%4,%5,%6,%7}, {%8,%9}, {%10,%11,%12,%13};"
        : "=f"(d[0]), "=f"(d[1]), "=f"(d[2]), "=f"(d[3])
        : "r"(a[0]), "r"(a[1]), "r"(a[2]), "r"(a[3]),
          "r"(b0), "r"(b1),
          "f"(0.0f), "f"(0.0f), "f"(0.0f), "f"(0.0f));
}

__device__ __forceinline__ float exp2sum2(float x, float y) {
    __half2 h = __floats2half2_rn(x, y);
    uint32_t u = *reinterpret_cast<uint32_t*>(&h);
    uint32_t r;
    asm("ex2.approx.f16x2 %0, %1;" : "=r"(r) : "r"(u));
    __half2 e = *reinterpret_cast<__half2*>(&r);
    float2 f = __half22float2(e);
    return f.x + f.y;
}

// ---------------- Kernel 1 (prep): V->bf16 (permuted)  +  A_pre ----------------
__global__ void k_prep(const int* __restrict__ tok, const float* __restrict__ emb,
                       const float* __restrict__ U, const float* __restrict__ V,
                       const float* __restrict__ b1, const float* __restrict__ b2) {
    int i = blockIdx.x * blockDim.x + threadIdx.x;
    if (i < VOCAB * 8) {           // one u32 (2 bf16) per thread
        int col = i >> 3, j = i & 7;
        __nv_bfloat162 p = __floats2bfloat162_rn(V[col * REC + 2 * j], V[col * REC + 2 * j + 1]);
        // destination slot: t = j&3, half = j>>2  ->  index col*8 + t*2 + half
        g_Vbp[col * 8 + ((j & 3) * 2 + (j >> 2))] = *reinterpret_cast<uint32_t*>(&p);
    }
    if (i < NROWS * REC) {
        int rid = i >> 4, r = i & 15;
        int tk  = tok[rid];
        const float* e = emb + (size_t)tk * EMB;
        const float* u = U + r * EMB;
        float acc = b1[r] + b2[r];
        #pragma unroll
        for (int k = 0; k < EMB; k++) acc = fmaf(e[k], u[k], acc);
        g_Apre[i] = acc;
    }
}

// ---------------- Kernel 2: serial recurrence ----------------
__global__ void k_rnn(const float* __restrict__ W, const float* __restrict__ h0v) {
    int lane = threadIdx.x;
    int b = blockIdx.x * 2 + (lane >> 4);
    int r = lane & 15;
    float w[REC];
    #pragma unroll
    for (int j = 0; j < REC; j++) w[j] = W[r * REC + j];
    float h = h0v[r];
    g_hidden[b * REC + r]  = __float2bfloat16(h);
    g_hiddenL[b * REC + r] = __float2bfloat16(h * L2E);
    float anext = g_Apre[b * REC + r];
    for (int t = 0; t < SEQ - 1; t++) {
        float a = anext;
        if (t < SEQ - 2) anext = g_Apre[((t + 1) * BATCH + b) * REC + r];
        float s0 = a, s1 = 0.0f;
        #pragma unroll
        for (int j = 0; j < REC; j += 2) {
            float hj = __shfl_sync(0xffffffffu, h, j,     16);
            float hk = __shfl_sync(0xffffffffu, h, j + 1, 16);
            s0 = fmaf(hj, w[j],     s0);
            s1 = fmaf(hk, w[j + 1], s1);
        }
        float z  = (s0 + s1) * (2.0f * L2E);
        float ez = ex2f(z);
        h = 1.0f - 2.0f * rcpf(ez + 1.0f);
        int idx = ((t + 1) * BATCH + b) * REC + r;
        g_hidden[idx]  = __float2bfloat16(h);
        g_hiddenL[idx] = __float2bfloat16(h * L2E);
    }
}

// ---- A-fragment loader: NF fragments of 16 rows each ----
__device__ __forceinline__ void load_afrag(uint32_t a[NF][4], const __nv_bfloat16* src,
                                           int tile, int g, int t) {
    const uint32_t* H = (const uint32_t*)src;
    #pragma unroll
    for (int f = 0; f < NF; f++) {
        int r0 = tile + f * 16 + g;
        int r1 = r0 + 8;
        a[f][0] = H[r0 * 8 + t];
        a[f][1] = H[r1 * 8 + t];
        a[f][2] = H[r0 * 8 + t + 4];
        a[f][3] = H[r1 * 8 + t + 4];
    }
}

// ---------------- Kernel 3 (pass 1): partial sum exp ----------------
// grid (NROWS/RPB=128, VS), 256 thr; warp covers VOCAB/VS/8 = 1000 cols.
__global__ void k_sum() {
    const int lane = threadIdx.x & 31, warp = threadIdx.x >> 5;
    const int g = lane >> 2, t = lane & 3;
    const int tile  = blockIdx.x * RPB;
    const int split = blockIdx.y;

    uint32_t a[NF][4];
    load_afrag(a, g_hiddenL, tile, g, t);

    const uint2* Vb = (const uint2*)g_Vbp;
    float s[NF][2];
    #pragma unroll
    for (int f = 0; f < NF; f++) s[f][0] = s[f][1] = 0.f;

    const int v0 = split * (VOCAB / VS) + warp * (VOCAB / VS / 8);
    const int vend = v0 + (VOCAB / VS / 8);
    uint2 b = Vb[(v0 + g) * 4 + t];
    for (int v = v0; v < vend; v += 8) {
        uint2 bn;
        if (v + 8 < vend) bn = Vb[(v + 8 + g) * 4 + t];
        #pragma unroll
        for (int f = 0; f < NF; f++) {
            float d[4];
            mma16816(d, a[f], b.x, b.y);
            s[f][0] += exp2sum2(d[0], d[1]);
            s[f][1] += exp2sum2(d[2], d[3]);
        }
        b = bn;
    }
    #pragma unroll
    for (int f = 0; f < NF; f++)
        #pragma unroll
        for (int m = 1; m <= 2; m <<= 1) {
            s[f][0] += __shfl_xor_sync(0xffffffffu, s[f][0], m);
            s[f][1] += __shfl_xor_sync(0xffffffffu, s[f][1], m);
        }
    __shared__ float red[8][RPB];
    if (t == 0) {
        #pragma unroll
        for (int f = 0; f < NF; f++) {
            red[warp][f * 16 + g]     = s[f][0];
            red[warp][f * 16 + g + 8] = s[f][1];
        }
    }
    __syncthreads();
    if (threadIdx.x < RPB) {
        float tot = 0.f;
        #pragma unroll
        for (int wq = 0; wq < 8; wq++) tot += red[wq][threadIdx.x];
        g_part[split][tile + threadIdx.x] = tot;
    }
}

__device__ __forceinline__ float row_const(int row) {
    float sres = g_part[0][row] + g_part[1][row] + g_part[2][row] + g_part[3][row];
    return LN2 * lg2f(sres);
}

// ---------------- Kernel 4 (pass 2): out = logit - ln(sum) ----------------
__global__ void k_out(float* __restrict__ out) {
    const int lane = threadIdx.x & 31, warp = threadIdx.x >> 5;
    const int g = lane >> 2, t = lane & 3;
    const int tile  = blockIdx.x * RPB;
    const int split = blockIdx.y;

    uint32_t a[NF][4];
    load_afrag(a, g_hidden, tile, g, t);

    float c[NF][2];
    float* base[NF][2];
    #pragma unroll
    for (int f = 0; f < NF; f++) {
        int r0 = tile + f * 16 + g;
        c[f][0] = row_const(r0);
        c[f][1] = row_const(r0 + 8);
        base[f][0] = out + (size_t)r0 * VOCAB + 2 * t;
        base[f][1] = base[f][0] + (size_t)8 * VOCAB;
    }

    const uint2* Vb = (const uint2*)g_Vbp;
    const int v0 = split * (VOCAB / VS) + warp * (VOCAB / VS / 8);
    const int vend = v0 + (VOCAB / VS / 8);
    uint2 b = Vb[(v0 + g) * 4 + t];
    for (int v = v0; v < vend; v += 8) {
        uint2 bn;
        if (v + 8 < vend) bn = Vb[(v + 8 + g) * 4 + t];
        #pragma unroll
        for (int f = 0; f < NF; f++) {
            float d[4];
            mma16816(d, a[f], b.x, b.y);
            __stcs((float2*)(base[f][0] + v), make_float2(d[0] - c[f][0], d[1] - c[f][0]));
            __stcs((float2*)(base[f][1] + v), make_float2(d[2] - c[f][1], d[3] - c[f][1]));
        }
        b = bn;
    }
}

extern "C" void kernel_launch(void* const* d_in, const int* in_sizes, int n_in,
                              void* d_out, int out_size) {
    const int*   tok = (const int*)d_in[0];
    const float* emb = (const float*)d_in[1];
    const float* U   = (const float*)d_in[2];
    const float* W   = (const float*)d_in[3];
    const float* V   = (const float*)d_in[4];
    const float* b1  = (const float*)d_in[5];
    const float* b2  = (const float*)d_in[6];
    const float* h0  = (const float*)d_in[7];
    float* out = (float*)d_out;

    k_prep<<<(VOCAB * 8 + 255) / 256, 256>>>(tok, emb, U, V, b1, b2);
    k_rnn<<<BATCH / 2, 32>>>(W, h0);
    dim3 grid2(NROWS / RPB, VS);
    k_sum<<<grid2, 256>>>();
    k_out<<<grid2, 256>>>(out);
}

// round 4
// speedup vs baseline: 1.2239x; 1.2239x over previous
#include <cuda_runtime.h>
#include <cuda_bf16.h>
#include <cuda_fp16.h>
#include <cstdint>

#define SEQ    256
#define BATCH  32
#define REC    16
#define EMB    32
#define VOCAB  32000
#define NROWS  (SEQ * BATCH)   // 8192
#define VS     5               // vocab splits: 2000 pairs / (5*8 warps) = 50 pairs/warp
#define RPB    32              // rows per block
#define NF     2               // MMA fragments per block
#define NPAIR  (VOCAB / 16)    // 2000 column-pairs (16 cols each)

// ---- scratch ----
__device__ float          g_Apre[NROWS * REC];
__device__ __nv_bfloat16  g_hidden[NROWS * REC];    // hidden, bf16
__device__ __nv_bfloat16  g_hiddenL[NROWS * REC];   // hidden * log2(e), bf16
__device__ uint4          g_Vq[NPAIR * 8 * 4];      // permuted V: [pair][slot n][t] -> {t0b0,t0b1,t1b0,t1b1}
__device__ float          g_part[VS][NROWS];

__device__ __forceinline__ float ex2f(float x) { float y; asm("ex2.approx.f32 %0, %1;" : "=f"(y) : "f"(x)); return y; }
__device__ __forceinline__ float lg2f(float x) { float y; asm("lg2.approx.f32 %0, %1;" : "=f"(y) : "f"(x)); return y; }
__device__ __forceinline__ float rcpf(float x) { float y; asm("rcp.approx.f32 %0, %1;" : "=f"(y) : "f"(x)); return y; }

#define L2E 1.4426950408889634f
#define LN2 0.6931471805599453f

__device__ __forceinline__ void mma16816(float d[4], const uint32_t a[4], uint32_t b0, uint32_t b1) {
    asm("mma.sync.aligned.m16n8k16.row.col.f32.bf16.bf16.f32 "
        "{%0,%1,%2,%3}, {%4,%5,%6,%7}, {%8,%9}, {%10,%11,%12,%13};"
        : "=f"(d[0]), "=f"(d[1]), "=f"(d[2]), "=f"(d[3])
        : "r"(a[0]), "r"(a[1]), "r"(a[2]), "r"(a[3]),
          "r"(b0), "r"(b1),
          "f"(0.0f), "f"(0.0f), "f"(0.0f), "f"(0.0f));
}

__device__ __forceinline__ float exp2sum2(float x, float y) {
    __half2 h = __floats2half2_rn(x, y);
    uint32_t u = *reinterpret_cast<uint32_t*>(&h);
    uint32_t r;
    asm("ex2.approx.f16x2 %0, %1;" : "=r"(r) : "r"(u));
    __half2 e = *reinterpret_cast<__half2*>(&r);
    float2 f = __half22float2(e);
    return f.x + f.y;
}

// ---------------- Kernel 1 (prep): V -> permuted bf16 uint4  +  A_pre ----------------
// Column permutation within each 16-col pair: w16 = 4*(n>>1) + 2*tile + (n&1)
// => MMA tile0 slot n covers vocab w16 {4q+r}, tile1 covers {4q+2+r}; thread t's
//    (d0[0],d0[1],d1[0],d1[1]) are vocab cols 4t..4t+3  -> float4 stores.
__global__ void k_prep(const int* __restrict__ tok, const float* __restrict__ emb,
                       const float* __restrict__ U, const float* __restrict__ V,
                       const float* __restrict__ b1, const float* __restrict__ b2) {
    int i = blockIdx.x * blockDim.x + threadIdx.x;
    if (i < VOCAB * 8) {           // one u32 (2 bf16) per thread
        int c = i >> 3, j = i & 7;
        int t = j & 3, half = j >> 2;
        __nv_bfloat162 p2 = __floats2bfloat162_rn(V[c * REC + 2 * j], V[c * REC + 2 * j + 1]);
        int p    = c >> 4;
        int w16  = c & 15;
        int tile = (w16 >> 1) & 1;
        int n    = ((w16 >> 2) << 1) | (w16 & 1);
        uint32_t* dst = (uint32_t*)g_Vq;
        dst[(((p * 8 + n) * 4 + t) << 2) + tile * 2 + half] = *reinterpret_cast<uint32_t*>(&p2);
    }
    if (i < NROWS * REC) {
        int rid = i >> 4, r = i & 15;
        int tk  = tok[rid];
        const float* e = emb + (size_t)tk * EMB;
        const float* u = U + r * EMB;
        float acc = b1[r] + b2[r];
        #pragma unroll
        for (int k = 0; k < EMB; k++) acc = fmaf(e[k], u[k], acc);
        g_Apre[i] = acc;
    }
}

// ---------------- Kernel 2: serial recurrence ----------------
__global__ void k_rnn(const float* __restrict__ W, const float* __restrict__ h0v) {
    int lane = threadIdx.x;
    int b = blockIdx.x * 2 + (lane >> 4);
    int r = lane & 15;
    float w[REC];
    #pragma unroll
    for (int j = 0; j < REC; j++) w[j] = W[r * REC + j];
    float h = h0v[r];
    g_hidden[b * REC + r]  = __float2bfloat16(h);
    g_hiddenL[b * REC + r] = __float2bfloat16(h * L2E);
    float anext = g_Apre[b * REC + r];
    for (int t = 0; t < SEQ - 1; t++) {
        float a = anext;
        if (t < SEQ - 2) anext = g_Apre[((t + 1) * BATCH + b) * REC + r];
        float s0 = a, s1 = 0.0f;
        #pragma unroll
        for (int j = 0; j < REC; j += 2) {
            float hj = __shfl_sync(0xffffffffu, h, j,     16);
            float hk = __shfl_sync(0xffffffffu, h, j + 1, 16);
            s0 = fmaf(hj, w[j],     s0);
            s1 = fmaf(hk, w[j + 1], s1);
        }
        float z  = (s0 + s1) * (2.0f * L2E);
        float ez = ex2f(z);
        h = 1.0f - 2.0f * rcpf(ez + 1.0f);
        int idx = ((t + 1) * BATCH + b) * REC + r;
        g_hidden[idx]  = __float2bfloat16(h);
        g_hiddenL[idx] = __float2bfloat16(h * L2E);
    }
}

// ---- A-fragment loader ----
__device__ __forceinline__ void load_afrag(uint32_t a[NF][4], const __nv_bfloat16* src,
                                           int tile, int g, int t) {
    const uint32_t* H = (const uint32_t*)src;
    #pragma unroll
    for (int f = 0; f < NF; f++) {
        int r0 = tile + f * 16 + g;
        int r1 = r0 + 8;
        a[f][0] = H[r0 * 8 + t];
        a[f][1] = H[r1 * 8 + t];
        a[f][2] = H[r0 * 8 + t + 4];
        a[f][3] = H[r1 * 8 + t + 4];
    }
}

// ---------------- Kernel 3 (pass 1): partial sum exp ----------------
// grid (256, VS), 256 thr; warp covers 50 pairs (800 cols).
__global__ void k_sum() {
    const int lane = threadIdx.x & 31, warp = threadIdx.x >> 5;
    const int g = lane >> 2, t = lane & 3;
    const int tile  = blockIdx.x * RPB;
    const int split = blockIdx.y;

    uint32_t a[NF][4];
    load_afrag(a, g_hiddenL, tile, g, t);

    float s[NF][2];
    #pragma unroll
    for (int f = 0; f < NF; f++) s[f][0] = s[f][1] = 0.f;

    const int p0 = split * (NPAIR / VS) + warp * (NPAIR / VS / 8);
    const int pend = p0 + (NPAIR / VS / 8);
    uint4 b = g_Vq[(p0 * 8 + g) * 4 + t];
    for (int p = p0; p < pend; p++) {
        uint4 bn;
        if (p + 1 < pend) bn = g_Vq[((p + 1) * 8 + g) * 4 + t];
        #pragma unroll
        for (int f = 0; f < NF; f++) {
            float d0[4], d1[4];
            mma16816(d0, a[f], b.x, b.y);
            mma16816(d1, a[f], b.z, b.w);
            s[f][0] += exp2sum2(d0[0], d0[1]) + exp2sum2(d1[0], d1[1]);
            s[f][1] += exp2sum2(d0[2], d0[3]) + exp2sum2(d1[2], d1[3]);
        }
        b = bn;
    }
    #pragma unroll
    for (int f = 0; f < NF; f++)
        #pragma unroll
        for (int m = 1; m <= 2; m <<= 1) {
            s[f][0] += __shfl_xor_sync(0xffffffffu, s[f][0], m);
            s[f][1] += __shfl_xor_sync(0xffffffffu, s[f][1], m);
        }
    __shared__ float red[8][RPB];
    if (t == 0) {
        #pragma unroll
        for (int f = 0; f < NF; f++) {
            red[warp][f * 16 + g]     = s[f][0];
            red[warp][f * 16 + g + 8] = s[f][1];
        }
    }
    __syncthreads();
    if (threadIdx.x < RPB) {
        float tot = 0.f;
        #pragma unroll
        for (int wq = 0; wq < 8; wq++) tot += red[wq][threadIdx.x];
        g_part[split][tile + threadIdx.x] = tot;
    }
}

__device__ __forceinline__ float row_const(int row) {
    float s = 0.f;
    #pragma unroll
    for (int q = 0; q < VS; q++) s += g_part[q][row];
    return LN2 * lg2f(s);
}

// ---------------- Kernel 4 (pass 2): out = logit - ln(sum), float4 stores ----------------
__global__ void k_out(float* __restrict__ out) {
    const int lane = threadIdx.x & 31, warp = threadIdx.x >> 5;
    const int g = lane >> 2, t = lane & 3;
    const int tile  = blockIdx.x * RPB;
    const int split = blockIdx.y;

    uint32_t a[NF][4];
    load_afrag(a, g_hidden, tile, g, t);

    float c[NF][2];
    float* base[NF][2];
    #pragma unroll
    for (int f = 0; f < NF; f++) {
        int r0 = tile + f * 16 + g;
        c[f][0] = row_const(r0);
        c[f][1] = row_const(r0 + 8);
        base[f][0] = out + (size_t)r0 * VOCAB + 4 * t;
        base[f][1] = base[f][0] + (size_t)8 * VOCAB;
    }

    const int p0 = split * (NPAIR / VS) + warp * (NPAIR / VS / 8);
    const int pend = p0 + (NPAIR / VS / 8);
    uint4 b = g_Vq[(p0 * 8 + g) * 4 + t];
    for (int p = p0; p < pend; p++) {
        uint4 bn;
        if (p + 1 < pend) bn = g_Vq[((p + 1) * 8 + g) * 4 + t];
        const int off = p * 16;
        #pragma unroll
        for (int f = 0; f < NF; f++) {
            float d0[4], d1[4];
            mma16816(d0, a[f], b.x, b.y);
            mma16816(d1, a[f], b.z, b.w);
            __stcs((float4*)(base[f][0] + off),
                   make_float4(d0[0] - c[f][0], d0[1] - c[f][0], d1[0] - c[f][0], d1[1] - c[f][0]));
            __stcs((float4*)(base[f][1] + off),
                   make_float4(d0[2] - c[f][1], d0[3] - c[f][1], d1[2] - c[f][1], d1[3] - c[f][1]));
        }
        b = bn;
    }
}

extern "C" void kernel_launch(void* const* d_in, const int* in_sizes, int n_in,
                              void* d_out, int out_size) {
    const int*   tok = (const int*)d_in[0];
    const float* emb = (const float*)d_in[1];
    const float* U   = (const float*)d_in[2];
    const float* W   = (const float*)d_in[3];
    const float* V   = (const float*)d_in[4];
    const float* b1  = (const float*)d_in[5];
    const float* b2  = (const float*)d_in[6];
    const float* h0  = (const float*)d_in[7];
    float* out = (float*)d_out;

    k_prep<<<(VOCAB * 8 + 255) / 256, 256>>>(tok, emb, U, V, b1, b2);
    k_rnn<<<BATCH / 2, 32>>>(W, h0);
    dim3 grid2(NROWS / RPB, VS);
    k_sum<<<grid2, 256>>>();
    k_out<<<grid2, 256>>>(out);
}

// round 5
// speedup vs baseline: 1.3788x; 1.1266x over previous
#include <cuda_runtime.h>
#include <cuda_bf16.h>
#include <cuda_fp16.h>
#include <cstdint>

#define SEQ    256
#define BATCH  32
#define REC    16
#define EMB    32
#define VOCAB  32000
#define NROWS  (SEQ * BATCH)   // 8192
#define VS     10              // vocab splits: 2000 pairs / (10*8 warps) = 25 pairs/warp
#define RPB    32              // rows per block
#define NF     2               // MMA fragments per block
#define NPAIR  (VOCAB / 16)    // 2000 column-pairs (16 cols each)

// ---- scratch ----
__device__ float          g_Apre[NROWS * REC];
__device__ __nv_bfloat16  g_hidden[NROWS * REC];    // hidden, bf16
__device__ __nv_bfloat16  g_hiddenL[NROWS * REC];   // hidden * log2(e), bf16
__device__ uint4          g_Vq[NPAIR * 8 * 4];      // permuted V (see k_prep)
__device__ float          g_part[VS][NROWS];

__device__ __forceinline__ float ex2f(float x) { float y; asm("ex2.approx.f32 %0, %1;" : "=f"(y) : "f"(x)); return y; }
__device__ __forceinline__ float lg2f(float x) { float y; asm("lg2.approx.f32 %0, %1;" : "=f"(y) : "f"(x)); return y; }
__device__ __forceinline__ float rcpf(float x) { float y; asm("rcp.approx.f32 %0, %1;" : "=f"(y) : "f"(x)); return y; }

#define L2E 1.4426950408889634f
#define LN2 0.6931471805599453f

__device__ __forceinline__ void mma16816(float d[4], const uint32_t a[4], uint32_t b0, uint32_t b1) {
    asm("mma.sync.aligned.m16n8k16.row.col.f32.bf16.bf16.f32 "
        "{%0,%1,%2,%3}, {%4,%5,%6,%7}, {%8,%9}, {%10,%11,%12,%13};"
        : "=f"(d[0]), "=f"(d[1]), "=f"(d[2]), "=f"(d[3])
        : "r"(a[0]), "r"(a[1]), "r"(a[2]), "r"(a[3]),
          "r"(b0), "r"(b1),
          "f"(0.0f), "f"(0.0f), "f"(0.0f), "f"(0.0f));
}

// 2^x, 2^y as half2 via one pack + one MUFU (inputs log2-domain, |x|<6)
__device__ __forceinline__ __half2 h2ex2(float x, float y) {
    uint32_t u, r;
    asm("cvt.rn.f16x2.f32 %0, %1, %2;" : "=r"(u) : "f"(y), "f"(x));
    asm("ex2.approx.f16x2 %0, %1;" : "=r"(r) : "r"(u));
    return *reinterpret_cast<__half2*>(&r);
}

// ---------------- Kernel 1 (prep): V -> permuted bf16 uint4  +  A_pre ----------------
// Within each 16-col pair: w16 = 4*(n>>1) + 2*tile + (n&1); thread t's
// (d0[0],d0[1],d1[0],d1[1]) become vocab cols 4t..4t+3 -> float4 stores.
__global__ void k_prep(const int* __restrict__ tok, const float* __restrict__ emb,
                       const float* __restrict__ U, const float* __restrict__ V,
                       const float* __restrict__ b1, const float* __restrict__ b2) {
    int i = blockIdx.x * blockDim.x + threadIdx.x;
    if (i < VOCAB * 8) {
        int c = i >> 3, j = i & 7;
        int t = j & 3, half = j >> 2;
        __nv_bfloat162 p2 = __floats2bfloat162_rn(V[c * REC + 2 * j], V[c * REC + 2 * j + 1]);
        int p    = c >> 4;
        int w16  = c & 15;
        int tile = (w16 >> 1) & 1;
        int n    = ((w16 >> 2) << 1) | (w16 & 1);
        uint32_t* dst = (uint32_t*)g_Vq;
        dst[(((p * 8 + n) * 4 + t) << 2) + tile * 2 + half] = *reinterpret_cast<uint32_t*>(&p2);
    }
    if (i < NROWS * REC) {
        int rid = i >> 4, r = i & 15;
        int tk  = tok[rid];
        const float* e = emb + (size_t)tk * EMB;
        const float* u = U + r * EMB;
        float acc = b1[r] + b2[r];
        #pragma unroll
        for (int k = 0; k < EMB; k++) acc = fmaf(e[k], u[k], acc);
        g_Apre[i] = acc;
    }
}

// ---------------- Kernel 2: serial recurrence ----------------
__global__ void k_rnn(const float* __restrict__ W, const float* __restrict__ h0v) {
    int lane = threadIdx.x;
    int b = blockIdx.x * 2 + (lane >> 4);
    int r = lane & 15;
    float w[REC];
    #pragma unroll
    for (int j = 0; j < REC; j++) w[j] = W[r * REC + j];
    float h = h0v[r];
    g_hidden[b * REC + r]  = __float2bfloat16(h);
    g_hiddenL[b * REC + r] = __float2bfloat16(h * L2E);
    float anext = g_Apre[b * REC + r];
    for (int t = 0; t < SEQ - 1; t++) {
        float a = anext;
        if (t < SEQ - 2) anext = g_Apre[((t + 1) * BATCH + b) * REC + r];
        float s0 = a, s1 = 0.f, s2 = 0.f, s3 = 0.f;   // 4 chains -> shorter dep chain
        #pragma unroll
        for (int j = 0; j < REC; j += 4) {
            float h0_ = __shfl_sync(0xffffffffu, h, j,     16);
            float h1_ = __shfl_sync(0xffffffffu, h, j + 1, 16);
            float h2_ = __shfl_sync(0xffffffffu, h, j + 2, 16);
            float h3_ = __shfl_sync(0xffffffffu, h, j + 3, 16);
            s0 = fmaf(h0_, w[j],     s0);
            s1 = fmaf(h1_, w[j + 1], s1);
            s2 = fmaf(h2_, w[j + 2], s2);
            s3 = fmaf(h3_, w[j + 3], s3);
        }
        float z  = ((s0 + s1) + (s2 + s3)) * (2.0f * L2E);
        float ez = ex2f(z);
        h = 1.0f - 2.0f * rcpf(ez + 1.0f);
        int idx = ((t + 1) * BATCH + b) * REC + r;
        g_hidden[idx]  = __float2bfloat16(h);
        g_hiddenL[idx] = __float2bfloat16(h * L2E);
    }
}

// ---- A-fragment loader ----
__device__ __forceinline__ void load_afrag(uint32_t a[NF][4], const __nv_bfloat16* src,
                                           int tile, int g, int t) {
    const uint32_t* H = (const uint32_t*)src;
    #pragma unroll
    for (int f = 0; f < NF; f++) {
        int r0 = tile + f * 16 + g;
        int r1 = r0 + 8;
        a[f][0] = H[r0 * 8 + t];
        a[f][1] = H[r1 * 8 + t];
        a[f][2] = H[r0 * 8 + t + 4];
        a[f][3] = H[r1 * 8 + t + 4];
    }
}

// ---------------- Kernel 3 (pass 1): partial sum exp, half2 accumulation ----------------
// grid (256, VS), 256 thr; warp covers 25 pairs (400 cols). Flush every 5 pairs.
__global__ void __launch_bounds__(256, 5) k_sum() {
    const int lane = threadIdx.x & 31, warp = threadIdx.x >> 5;
    const int g = lane >> 2, t = lane & 3;
    const int tile  = blockIdx.x * RPB;
    const int split = blockIdx.y;

    uint32_t a[NF][4];
    load_afrag(a, g_hiddenL, tile, g, t);

    float s[NF][2];
    __half2 hacc[NF][2];
    #pragma unroll
    for (int f = 0; f < NF; f++) {
        s[f][0] = s[f][1] = 0.f;
        hacc[f][0] = hacc[f][1] = __float2half2_rn(0.f);
    }

    const int p0 = split * (NPAIR / VS) + warp * (NPAIR / VS / 8);
    uint4 b = g_Vq[(p0 * 8 + g) * 4 + t];
    #pragma unroll 1
    for (int blk = 0; blk < 5; blk++) {            // 5 flush blocks of 5 pairs
        #pragma unroll
        for (int q = 0; q < 5; q++) {
            int p = p0 + blk * 5 + q;
            uint4 bn;
            if (blk * 5 + q < 24) bn = g_Vq[((p + 1) * 8 + g) * 4 + t];
            #pragma unroll
            for (int f = 0; f < NF; f++) {
                float d0[4], d1[4];
                mma16816(d0, a[f], b.x, b.y);
                mma16816(d1, a[f], b.z, b.w);
                hacc[f][0] = __hadd2(hacc[f][0], h2ex2(d0[0], d0[1]));
                hacc[f][0] = __hadd2(hacc[f][0], h2ex2(d1[0], d1[1]));
                hacc[f][1] = __hadd2(hacc[f][1], h2ex2(d0[2], d0[3]));
                hacc[f][1] = __hadd2(hacc[f][1], h2ex2(d1[2], d1[3]));
            }
            b = bn;
        }
        #pragma unroll
        for (int f = 0; f < NF; f++) {
            float2 f0 = __half22float2(hacc[f][0]);
            float2 f1 = __half22float2(hacc[f][1]);
            s[f][0] += f0.x + f0.y;
            s[f][1] += f1.x + f1.y;
            hacc[f][0] = hacc[f][1] = __float2half2_rn(0.f);
        }
    }
    #pragma unroll
    for (int f = 0; f < NF; f++)
        #pragma unroll
        for (int m = 1; m <= 2; m <<= 1) {
            s[f][0] += __shfl_xor_sync(0xffffffffu, s[f][0], m);
            s[f][1] += __shfl_xor_sync(0xffffffffu, s[f][1], m);
        }
    __shared__ float red[8][RPB];
    if (t == 0) {
        #pragma unroll
        for (int f = 0; f < NF; f++) {
            red[warp][f * 16 + g]     = s[f][0];
            red[warp][f * 16 + g + 8] = s[f][1];
        }
    }
    __syncthreads();
    if (threadIdx.x < RPB) {
        float tot = 0.f;
        #pragma unroll
        for (int wq = 0; wq < 8; wq++) tot += red[wq][threadIdx.x];
        g_part[split][tile + threadIdx.x] = tot;
    }
}

__device__ __forceinline__ float row_const(int row) {
    float s = 0.f;
    #pragma unroll
    for (int q = 0; q < VS; q++) s += g_part[q][row];
    return LN2 * lg2f(s);
}

// ---------------- Kernel 4 (pass 2): out = logit - ln(sum), float4 stores ----------------
__global__ void __launch_bounds__(256, 5) k_out(float* __restrict__ out) {
    const int lane = threadIdx.x & 31, warp = threadIdx.x >> 5;
    const int g = lane >> 2, t = lane & 3;
    const int tile  = blockIdx.x * RPB;
    const int split = blockIdx.y;

    uint32_t a[NF][4];
    load_afrag(a, g_hidden, tile, g, t);

    float c[NF][2];
    #pragma unroll
    for (int f = 0; f < NF; f++) {
        c[f][0] = row_const(tile + f * 16 + g);
        c[f][1] = row_const(tile + f * 16 + g + 8);
    }
    // single base pointer; row offsets folded into store immediates
    float* base = out + (size_t)(tile + g) * VOCAB + 4 * t;

    const int p0 = split * (NPAIR / VS) + warp * (NPAIR / VS / 8);
    const int pend = p0 + (NPAIR / VS / 8);
    uint4 b = g_Vq[(p0 * 8 + g) * 4 + t];
    for (int p = p0; p < pend; p++) {
        uint4 bn;
        if (p + 1 < pend) bn = g_Vq[((p + 1) * 8 + g) * 4 + t];
        float* bp = base + p * 16;
        #pragma unroll
        for (int f = 0; f < NF; f++) {
            float d0[4], d1[4];
            mma16816(d0, a[f], b.x, b.y);
            mma16816(d1, a[f], b.z, b.w);
            __stcs((float4*)(bp + (size_t)(f * 16)     * VOCAB),
                   make_float4(d0[0] - c[f][0], d0[1] - c[f][0], d1[0] - c[f][0], d1[1] - c[f][0]));
            __stcs((float4*)(bp + (size_t)(f * 16 + 8) * VOCAB),
                   make_float4(d0[2] - c[f][1], d0[3] - c[f][1], d1[2] - c[f][1], d1[3] - c[f][1]));
        }
        b = bn;
    }
}

extern "C" void kernel_launch(void* const* d_in, const int* in_sizes, int n_in,
                              void* d_out, int out_size) {
    const int*   tok = (const int*)d_in[0];
    const float* emb = (const float*)d_in[1];
    const float* U   = (const float*)d_in[2];
    const float* W   = (const float*)d_in[3];
    const float* V   = (const float*)d_in[4];
    const float* b1  = (const float*)d_in[5];
    const float* b2  = (const float*)d_in[6];
    const float* h0  = (const float*)d_in[7];
    float* out = (float*)d_out;

    k_prep<<<(VOCAB * 8 + 255) / 256, 256>>>(tok, emb, U, V, b1, b2);
    k_rnn<<<BATCH / 2, 32>>>(W, h0);
    dim3 grid2(NROWS / RPB, VS);
    k_sum<<<grid2, 256>>>();
    k_out<<<grid2, 256>>>(out);
}